// round 1
// baseline (speedup 1.0000x reference)
#include <cuda_runtime.h>
#include <math.h>

#define SEQ    4096
#define DMODEL 1024

#define BM 128
#define BN 128
#define BK 8

// Scratch (device globals: allocation-free kernel_launch)
__device__ float g_Q [SEQ * DMODEL];
__device__ float g_Km[SEQ * DMODEL];
__device__ float g_Vm[SEQ * DMODEL];
__device__ float g_S [(size_t)SEQ * SEQ];

// ---------------------------------------------------------------------------
// Stage 1: Q/K/V = X @ W{q,k,v}   (NN GEMM, M=4096, N=1024, K=1024, z picks W)
// ---------------------------------------------------------------------------
__global__ __launch_bounds__(256) void qkv_kernel(
    const float* __restrict__ X,
    const float* __restrict__ Wq,
    const float* __restrict__ Wk,
    const float* __restrict__ Wv)
{
    __shared__ float As[BK][BM];
    __shared__ float Bs[BK][BN];

    const float* B = (blockIdx.z == 0) ? Wq : (blockIdx.z == 1) ? Wk : Wv;
    float*       C = (blockIdx.z == 0) ? g_Q : (blockIdx.z == 1) ? g_Km : g_Vm;

    const int K = DMODEL, N = DMODEL;
    const int m0 = blockIdx.y * BM, n0 = blockIdx.x * BN;
    const int tid  = threadIdx.x;
    const int aRow = tid >> 1,  aCol = (tid & 1) * 4;
    const int bRow = tid >> 5,  bCol = (tid & 31) * 4;
    const int ty   = tid >> 4,  tx   = tid & 15;

    float acc[8][8];
#pragma unroll
    for (int i = 0; i < 8; i++)
#pragma unroll
        for (int j = 0; j < 8; j++) acc[i][j] = 0.0f;

    for (int k0 = 0; k0 < K; k0 += BK) {
        float4 av = *(const float4*)(X + (size_t)(m0 + aRow) * K + k0 + aCol);
        As[aCol + 0][aRow] = av.x;
        As[aCol + 1][aRow] = av.y;
        As[aCol + 2][aRow] = av.z;
        As[aCol + 3][aRow] = av.w;
        float4 bv = *(const float4*)(B + (size_t)(k0 + bRow) * N + n0 + bCol);
        *(float4*)(&Bs[bRow][bCol]) = bv;
        __syncthreads();
#pragma unroll
        for (int k = 0; k < BK; k++) {
            float ra[8], rb[8];
            *(float4*)(ra)     = *(const float4*)(&As[k][ty * 8]);
            *(float4*)(ra + 4) = *(const float4*)(&As[k][ty * 8 + 4]);
            *(float4*)(rb)     = *(const float4*)(&Bs[k][tx * 8]);
            *(float4*)(rb + 4) = *(const float4*)(&Bs[k][tx * 8 + 4]);
#pragma unroll
            for (int i = 0; i < 8; i++)
#pragma unroll
                for (int j = 0; j < 8; j++) acc[i][j] = fmaf(ra[i], rb[j], acc[i][j]);
        }
        __syncthreads();
    }

#pragma unroll
    for (int i = 0; i < 8; i++) {
        float* crow = C + (size_t)(m0 + ty * 8 + i) * N + n0 + tx * 8;
        *(float4*)(crow)     = make_float4(acc[i][0], acc[i][1], acc[i][2], acc[i][3]);
        *(float4*)(crow + 4) = make_float4(acc[i][4], acc[i][5], acc[i][6], acc[i][7]);
    }
}

// ---------------------------------------------------------------------------
// Stage 2: S = (Q @ K^T) * scale, causal mask, lower-triangular blocks only.
// NT GEMM: both Q and K are row-major [rows, 1024] with K-dim contiguous.
// ---------------------------------------------------------------------------
__global__ __launch_bounds__(256) void scores_kernel()
{
    // linear block id -> lower-triangular (br, bc), bc <= br
    int i  = (int)blockIdx.x;
    int br = (int)((sqrtf(8.0f * (float)i + 1.0f) - 1.0f) * 0.5f);
    while ((br + 1) * (br + 2) / 2 <= i) br++;
    while (br * (br + 1) / 2 > i)        br--;
    int bc = i - br * (br + 1) / 2;

    __shared__ float As[BK][BM];
    __shared__ float Bs[BK][BN];

    const int K  = DMODEL;
    const int m0 = br * BM, n0 = bc * BN;
    const int tid  = threadIdx.x;
    const int aRow = tid >> 1, aCol = (tid & 1) * 4;
    const int bN   = tid >> 1, bK   = (tid & 1) * 4;
    const int ty   = tid >> 4, tx   = tid & 15;
    const float scale = 0.03125f;   // 1/sqrt(1024)

    float acc[8][8];
#pragma unroll
    for (int ii = 0; ii < 8; ii++)
#pragma unroll
        for (int j = 0; j < 8; j++) acc[ii][j] = 0.0f;

    for (int k0 = 0; k0 < K; k0 += BK) {
        float4 av = *(const float4*)(g_Q + (size_t)(m0 + aRow) * K + k0 + aCol);
        As[aCol + 0][aRow] = av.x;
        As[aCol + 1][aRow] = av.y;
        As[aCol + 2][aRow] = av.z;
        As[aCol + 3][aRow] = av.w;
        float4 bv = *(const float4*)(g_Km + (size_t)(n0 + bN) * K + k0 + bK);
        Bs[bK + 0][bN] = bv.x;
        Bs[bK + 1][bN] = bv.y;
        Bs[bK + 2][bN] = bv.z;
        Bs[bK + 3][bN] = bv.w;
        __syncthreads();
#pragma unroll
        for (int k = 0; k < BK; k++) {
            float ra[8], rb[8];
            *(float4*)(ra)     = *(const float4*)(&As[k][ty * 8]);
            *(float4*)(ra + 4) = *(const float4*)(&As[k][ty * 8 + 4]);
            *(float4*)(rb)     = *(const float4*)(&Bs[k][tx * 8]);
            *(float4*)(rb + 4) = *(const float4*)(&Bs[k][tx * 8 + 4]);
#pragma unroll
            for (int ii = 0; ii < 8; ii++)
#pragma unroll
                for (int j = 0; j < 8; j++) acc[ii][j] = fmaf(ra[ii], rb[j], acc[ii][j]);
        }
        __syncthreads();
    }

#pragma unroll
    for (int ii = 0; ii < 8; ii++) {
        int row = m0 + ty * 8 + ii;
        float* srow = g_S + (size_t)row * SEQ + n0 + tx * 8;
        if (br != bc) {
            *(float4*)(srow)     = make_float4(acc[ii][0] * scale, acc[ii][1] * scale,
                                               acc[ii][2] * scale, acc[ii][3] * scale);
            *(float4*)(srow + 4) = make_float4(acc[ii][4] * scale, acc[ii][5] * scale,
                                               acc[ii][6] * scale, acc[ii][7] * scale);
        } else {
#pragma unroll
            for (int j = 0; j < 8; j++) {
                int col = n0 + tx * 8 + j;
                srow[j] = (col <= row) ? acc[ii][j] * scale : -INFINITY;
            }
        }
    }
}

// ---------------------------------------------------------------------------
// Stage 3: row softmax over S, in place. Row r covers cols [0, roundup128(r+1)).
// Masked (-inf) entries become exact 0, so stage 4 can read the padded region.
// ---------------------------------------------------------------------------
__global__ __launch_bounds__(256) void softmax_kernel()
{
    const int r   = (int)blockIdx.x;
    const int L   = (((r >> 7) + 1) << 7);         // padded row length
    float* row    = g_S + (size_t)r * SEQ;
    const int tid = threadIdx.x;
    __shared__ float red[256];

    float v[16];
    int   cnt = 0;
    float mx  = -INFINITY;
    for (int c = tid; c < L; c += 256) {
        float t = row[c];
        v[cnt++] = t;
        mx = fmaxf(mx, t);
    }
    red[tid] = mx;
    __syncthreads();
#pragma unroll
    for (int s = 128; s > 0; s >>= 1) {
        if (tid < s) red[tid] = fmaxf(red[tid], red[tid + s]);
        __syncthreads();
    }
    mx = red[0];
    __syncthreads();

    float sum = 0.0f;
    for (int j = 0; j < cnt; j++) {
        v[j] = expf(v[j] - mx);   // exp(-inf) == 0 for masked entries
        sum += v[j];
    }
    red[tid] = sum;
    __syncthreads();
#pragma unroll
    for (int s = 128; s > 0; s >>= 1) {
        if (tid < s) red[tid] += red[tid + s];
        __syncthreads();
    }
    const float rinv = 1.0f / red[0];

    cnt = 0;
    for (int c = tid; c < L; c += 256) row[c] = v[cnt++] * rinv;
}

// ---------------------------------------------------------------------------
// Stage 4: O = P @ V (NN GEMM). Per block-row, K-loop ends at (block_row+1)*128
// (everything beyond is exactly zero and was never written).
// ---------------------------------------------------------------------------
__global__ __launch_bounds__(256) void pv_kernel(float* __restrict__ out)
{
    __shared__ float As[BK][BM];
    __shared__ float Bs[BK][BN];

    const int N  = DMODEL;
    const int m0 = blockIdx.y * BM, n0 = blockIdx.x * BN;
    const int Kend = m0 + BM;
    const int tid  = threadIdx.x;
    const int aRow = tid >> 1,  aCol = (tid & 1) * 4;
    const int bRow = tid >> 5,  bCol = (tid & 31) * 4;
    const int ty   = tid >> 4,  tx   = tid & 15;

    float acc[8][8];
#pragma unroll
    for (int i = 0; i < 8; i++)
#pragma unroll
        for (int j = 0; j < 8; j++) acc[i][j] = 0.0f;

    for (int k0 = 0; k0 < Kend; k0 += BK) {
        float4 av = *(const float4*)(g_S + (size_t)(m0 + aRow) * SEQ + k0 + aCol);
        As[aCol + 0][aRow] = av.x;
        As[aCol + 1][aRow] = av.y;
        As[aCol + 2][aRow] = av.z;
        As[aCol + 3][aRow] = av.w;
        float4 bv = *(const float4*)(g_Vm + (size_t)(k0 + bRow) * N + n0 + bCol);
        *(float4*)(&Bs[bRow][bCol]) = bv;
        __syncthreads();
#pragma unroll
        for (int k = 0; k < BK; k++) {
            float ra[8], rb[8];
            *(float4*)(ra)     = *(const float4*)(&As[k][ty * 8]);
            *(float4*)(ra + 4) = *(const float4*)(&As[k][ty * 8 + 4]);
            *(float4*)(rb)     = *(const float4*)(&Bs[k][tx * 8]);
            *(float4*)(rb + 4) = *(const float4*)(&Bs[k][tx * 8 + 4]);
#pragma unroll
            for (int i = 0; i < 8; i++)
#pragma unroll
                for (int j = 0; j < 8; j++) acc[i][j] = fmaf(ra[i], rb[j], acc[i][j]);
        }
        __syncthreads();
    }

#pragma unroll
    for (int i = 0; i < 8; i++) {
        float* crow = out + (size_t)(m0 + ty * 8 + i) * N + n0 + tx * 8;
        *(float4*)(crow)     = make_float4(acc[i][0], acc[i][1], acc[i][2], acc[i][3]);
        *(float4*)(crow + 4) = make_float4(acc[i][4], acc[i][5], acc[i][6], acc[i][7]);
    }
}

// ---------------------------------------------------------------------------
extern "C" void kernel_launch(void* const* d_in, const int* in_sizes, int n_in,
                              void* d_out, int out_size)
{
    const float* x  = (const float*)d_in[0];
    const float* Wq = (const float*)d_in[1];
    const float* Wk = (const float*)d_in[2];
    const float* Wv = (const float*)d_in[3];
    float* out = (float*)d_out;

    (void)in_sizes; (void)n_in; (void)out_size;

    // Stage 1: QKV projections
    {
        dim3 grid(DMODEL / BN, SEQ / BM, 3);
        qkv_kernel<<<grid, 256>>>(x, Wq, Wk, Wv);
    }
    // Stage 2: causal scaled scores (lower-triangular blocks)
    {
        const int nTri = (SEQ / BM) * (SEQ / BM + 1) / 2;  // 528
        scores_kernel<<<nTri, 256>>>();
    }
    // Stage 3: row softmax
    softmax_kernel<<<SEQ, 256>>>();
    // Stage 4: O = P @ V
    {
        dim3 grid(DMODEL / BN, SEQ / BM);
        pv_kernel<<<grid, 256>>>(out);
    }
}

// round 3
// speedup vs baseline: 2.4987x; 2.4987x over previous
#include <cuda_runtime.h>
#include <cuda_bf16.h>
#include <math.h>
#include <stdint.h>

#define SEQ 4096
#define DM  1024
#define TM  128
#define TN  128
#define BK  32

#define NTHREADS 256

// smem buffer layout (per stage): Ahi[128*80B] Alo Bhi Blo
#define A_PITCH  80        // bytes per row (64B data + 16B pad) -> conflict-free ldmatrix
#define AHI_OFF  0
#define ALO_OFF  10240
#define BHI_OFF  20480
#define BLO_OFF  30720
#define BUFB     40960
#define SMEM_BYTES (2 * BUFB)

// ---------------- scratch (device globals; allocation-free) ----------------
__device__ __nv_bfloat16 g_Xhi[SEQ * DM],  g_Xlo[SEQ * DM];
__device__ __nv_bfloat16 g_Qhi[SEQ * DM],  g_Qlo[SEQ * DM];
__device__ __nv_bfloat16 g_Khi[SEQ * DM],  g_Klo[SEQ * DM];
__device__ __nv_bfloat16 g_Vhi[SEQ * DM],  g_Vlo[SEQ * DM];
__device__ __nv_bfloat16 g_Wthi[3 * DM * DM], g_Wtlo[3 * DM * DM]; // W^T [n][k]
__device__ __nv_bfloat16 g_Phi[(size_t)SEQ * SEQ], g_Plo[(size_t)SEQ * SEQ];
__device__ float         g_S  [(size_t)SEQ * SEQ];

// ---------------- PTX helpers (baseline PTX only; no arch-'a' features) ----
__device__ __forceinline__ uint32_t smem_u32(const void* p) {
    uint32_t a;
    asm("{ .reg .u64 t; cvta.to.shared.u64 t, %1; cvt.u32.u64 %0, t; }" : "=r"(a) : "l"(p));
    return a;
}

#define CP16(dst, src) \
    asm volatile("cp.async.cg.shared.global [%0], [%1], 16;" :: "r"(dst), "l"(src) : "memory")
#define CP_COMMIT() asm volatile("cp.async.commit_group;" ::: "memory")
#define CP_WAIT(n)  asm volatile("cp.async.wait_group %0;" :: "n"(n) : "memory")

#define LDSM_X4(r, addr) \
    asm volatile("ldmatrix.sync.aligned.m8n8.x4.shared.b16 {%0,%1,%2,%3}, [%4];" \
        : "=r"((r)[0]), "=r"((r)[1]), "=r"((r)[2]), "=r"((r)[3]) : "r"(addr))
#define LDSM_X2(r, addr) \
    asm volatile("ldmatrix.sync.aligned.m8n8.x2.shared.b16 {%0,%1}, [%2];" \
        : "=r"((r)[0]), "=r"((r)[1]) : "r"(addr))
#define LDSM_X2T(r, addr) \
    asm volatile("ldmatrix.sync.aligned.m8n8.x2.trans.shared.b16 {%0,%1}, [%2];" \
        : "=r"((r)[0]), "=r"((r)[1]) : "r"(addr))

#define MMA_BF16(d, a, b) \
    asm volatile("mma.sync.aligned.m16n8k16.row.col.f32.bf16.bf16.f32 " \
        "{%0,%1,%2,%3}, {%4,%5,%6,%7}, {%8,%9}, {%0,%1,%2,%3};" \
        : "+f"((d)[0]), "+f"((d)[1]), "+f"((d)[2]), "+f"((d)[3]) \
        : "r"((a)[0]), "r"((a)[1]), "r"((a)[2]), "r"((a)[3]), "r"((b)[0]), "r"((b)[1]))

// ---------------- split helpers ----------------
__device__ __forceinline__ void split1(float v, __nv_bfloat16& h, __nv_bfloat16& l) {
    h = __float2bfloat16(v);
    l = __float2bfloat16(v - __bfloat162float(h));
}
__device__ __forceinline__ void split2(float x, float y, uint32_t& hu, uint32_t& lu) {
    __nv_bfloat162 h, l;
    h.x = __float2bfloat16(x);
    h.y = __float2bfloat16(y);
    l.x = __float2bfloat16(x - __bfloat162float(h.x));
    l.y = __float2bfloat16(y - __bfloat162float(h.y));
    hu = *reinterpret_cast<uint32_t*>(&h);
    lu = *reinterpret_cast<uint32_t*>(&l);
}

// ---------------------------------------------------------------------------
// X split: fp32 -> hi/lo bf16
// ---------------------------------------------------------------------------
__global__ __launch_bounds__(256) void xsplit_kernel(const float* __restrict__ x)
{
    int i = (blockIdx.x * 256 + threadIdx.x) * 4;
    float4 v = *(const float4*)(x + i);
    uint32_t h0, l0, h1, l1;
    split2(v.x, v.y, h0, l0);
    split2(v.z, v.w, h1, l1);
    *(uint2*)(g_Xhi + i) = make_uint2(h0, h1);
    *(uint2*)(g_Xlo + i) = make_uint2(l0, l1);
}

// ---------------------------------------------------------------------------
// W transpose + split: W [k][n] fp32 -> Wt hi/lo [n][k] bf16
// ---------------------------------------------------------------------------
__global__ __launch_bounds__(256) void wtrans_kernel(
    const float* __restrict__ Wq, const float* __restrict__ Wk, const float* __restrict__ Wv)
{
    __shared__ float t[32][33];
    const float* W = (blockIdx.z == 0) ? Wq : (blockIdx.z == 1) ? Wk : Wv;
    const size_t zoff = (size_t)blockIdx.z * DM * DM;
    const int n0 = blockIdx.x * 32, k0 = blockIdx.y * 32;
    const int tx = threadIdx.x, ty = threadIdx.y;  // (32, 8)

#pragma unroll
    for (int j = 0; j < 32; j += 8)
        t[ty + j][tx] = W[(size_t)(k0 + ty + j) * DM + n0 + tx];
    __syncthreads();
#pragma unroll
    for (int j = 0; j < 32; j += 8) {
        float v = t[tx][ty + j];
        __nv_bfloat16 h, l; split1(v, h, l);
        size_t o = zoff + (size_t)(n0 + ty + j) * DM + k0 + tx;
        g_Wthi[o] = h; g_Wtlo[o] = l;
    }
}

// ---------------------------------------------------------------------------
// Unified split-bf16 mma.sync GEMM. 128x128 CTA tile, 8 warps of 32x64, BK=32,
// cp.async double-buffered.
//  MODE 0: proj  (z: 0=Q,1=K,2=V). A=Xhi/lo, B=Wt[z]. out split bf16.
//  MODE 3: scores. A=Qhi/lo, B=Khi/lo. tri grid; out g_S fp32 (scaled+masked).
//  MODE 4: PV. A=Phi/lo, B=Vhi/lo stored [k][n] (trans ldmatrix). out fp32.
// ---------------------------------------------------------------------------
template<int MODE>
__global__ __launch_bounds__(NTHREADS, 1) void hgemm(float* __restrict__ Oext)
{
    extern __shared__ char smem[];
    const uint32_t sb = smem_u32(smem);
    const int tid  = threadIdx.x;
    const int wid  = tid >> 5;
    const int lane = tid & 31;
    const int wr   = wid & 3;        // warp row (32 rows)
    const int wc   = wid >> 2;       // warp col (64 cols)

    int m0, n0, br = 0, bc = 0;
    if (MODE == 3) {
        int i = (int)blockIdx.x;
        br = (int)((sqrtf(8.0f * (float)i + 1.0f) - 1.0f) * 0.5f);
        while ((br + 1) * (br + 2) / 2 <= i) br++;
        while (br * (br + 1) / 2 > i)        br--;
        bc = i - br * (br + 1) / 2;
        m0 = br * TM; n0 = bc * TN;
    } else {
        m0 = blockIdx.y * TM; n0 = blockIdx.x * TN;
    }

    const __nv_bfloat16 *Ah, *Al, *Bh, *Bl;
    int lda, ldb, Kext;
    if (MODE == 0) {
        Ah = g_Xhi; Al = g_Xlo; lda = DM; Kext = DM; ldb = DM;
        Bh = g_Wthi + (size_t)blockIdx.z * DM * DM;
        Bl = g_Wtlo + (size_t)blockIdx.z * DM * DM;
    } else if (MODE == 3) {
        Ah = g_Qhi; Al = g_Qlo; lda = DM; Kext = DM; ldb = DM;
        Bh = g_Khi; Bl = g_Klo;
    } else {
        Ah = g_Phi; Al = g_Plo; lda = SEQ; Kext = m0 + TM; ldb = DM;
        Bh = g_Vhi; Bl = g_Vlo;   // [k][n], n contiguous
    }

    float acc[2][8][4];
#pragma unroll
    for (int mi = 0; mi < 2; mi++)
#pragma unroll
        for (int nf = 0; nf < 8; nf++)
#pragma unroll
            for (int q = 0; q < 4; q++) acc[mi][nf][q] = 0.0f;

    const int nch = Kext / BK;

    // ---- chunk loader
    auto load_chunk = [&](int c) {
        const int k0  = c * BK;
        const uint32_t base = sb + (uint32_t)(c & 1) * BUFB;
        if (MODE == 4) {
            // A: 128 rows x 32 k (4 chunks of 16B)
            for (int u = tid; u < 512; u += NTHREADS) {
                int row = u >> 2, ch = u & 3;
                size_t go = (size_t)(m0 + row) * lda + k0 + ch * 8;
                uint32_t da = base + AHI_OFF + row * A_PITCH + ch * 16;
                CP16(da,         Ah + go);
                CP16(da + ALO_OFF, Al + go);
            }
            // B: 32 k-rows x 128 n, XOR-swizzled chunks
            for (int u = tid; u < 512; u += NTHREADS) {
                int k = u >> 4, ch = u & 15;
                size_t go = (size_t)(k0 + k) * ldb + n0 + ch * 8;
                uint32_t db = base + BHI_OFF + k * 256 + ((ch ^ (k & 7)) << 4);
                CP16(db,             Bh + go);
                CP16(db + (BLO_OFF - BHI_OFF), Bl + go);
            }
        } else {
            for (int u = tid; u < 512; u += NTHREADS) {
                int row = u >> 2, ch = u & 3;
                size_t ga = (size_t)(m0 + row) * lda + k0 + ch * 8;
                size_t gb = (size_t)(n0 + row) * ldb + k0 + ch * 8;
                uint32_t da = base + AHI_OFF + row * A_PITCH + ch * 16;
                uint32_t db = base + BHI_OFF + row * A_PITCH + ch * 16;
                CP16(da,           Ah + ga);
                CP16(da + ALO_OFF, Al + ga);
                CP16(db,           Bh + gb);
                CP16(db + (BLO_OFF - BHI_OFF), Bl + gb);
            }
        }
    };

    load_chunk(0);
    CP_COMMIT();

    for (int c = 0; c < nch; c++) {
        if (c + 1 < nch) { load_chunk(c + 1); CP_COMMIT(); CP_WAIT(1); }
        else             { CP_WAIT(0); }
        __syncthreads();

        const uint32_t base = sb + (uint32_t)(c & 1) * BUFB;
#pragma unroll
        for (int ks = 0; ks < 2; ks++) {
            uint32_t ah[2][4], al[2][4];
#pragma unroll
            for (int mi = 0; mi < 2; mi++) {
                uint32_t aaddr = base + AHI_OFF
                    + (wr * 32 + mi * 16 + (lane & 15)) * A_PITCH
                    + (ks * 2 + (lane >> 4)) * 16;
                LDSM_X4(ah[mi], aaddr);
                LDSM_X4(al[mi], aaddr + ALO_OFF);
            }
#pragma unroll
            for (int nf = 0; nf < 8; nf++) {
                uint32_t bh[2], bl[2];
                if (MODE == 4) {
                    int klo = ks * 16 + (lane & 15);
                    uint32_t baddr = base + BHI_OFF + klo * 256
                        + (((wc * 8 + nf) ^ (klo & 7)) << 4);
                    LDSM_X2T(bh, baddr);
                    LDSM_X2T(bl, baddr + (BLO_OFF - BHI_OFF));
                } else {
                    uint32_t baddr = base + BHI_OFF
                        + (wc * 64 + nf * 8 + (lane & 7)) * A_PITCH
                        + (ks * 2 + ((lane >> 3) & 1)) * 16;
                    LDSM_X2(bh, baddr);
                    LDSM_X2(bl, baddr + (BLO_OFF - BHI_OFF));
                }
#pragma unroll
                for (int mi = 0; mi < 2; mi++) {
                    MMA_BF16(acc[mi][nf], ah[mi], bh);
                    MMA_BF16(acc[mi][nf], ah[mi], bl);
                    MMA_BF16(acc[mi][nf], al[mi], bh);
                }
            }
        }
        __syncthreads();
    }

    // ---- epilogue
    const int rb = m0 + wr * 32 + (lane >> 2);
    const int cb = n0 + wc * 64 + 2 * (lane & 3);
    const float scale = 0.03125f;   // 1/sqrt(1024), MODE 3 only

#pragma unroll
    for (int mi = 0; mi < 2; mi++) {
#pragma unroll
        for (int nf = 0; nf < 8; nf++) {
            int r0 = rb + mi * 16;
            int cc = cb + nf * 8;
            float v00 = acc[mi][nf][0], v01 = acc[mi][nf][1];
            float v10 = acc[mi][nf][2], v11 = acc[mi][nf][3];
            if (MODE == 0) {
                __nv_bfloat16* Oh = (blockIdx.z == 0) ? g_Qhi : (blockIdx.z == 1) ? g_Khi : g_Vhi;
                __nv_bfloat16* Ol = (blockIdx.z == 0) ? g_Qlo : (blockIdx.z == 1) ? g_Klo : g_Vlo;
                uint32_t h, l;
                split2(v00, v01, h, l);
                *(uint32_t*)(Oh + (size_t)r0 * DM + cc) = h;
                *(uint32_t*)(Ol + (size_t)r0 * DM + cc) = l;
                split2(v10, v11, h, l);
                *(uint32_t*)(Oh + (size_t)(r0 + 8) * DM + cc) = h;
                *(uint32_t*)(Ol + (size_t)(r0 + 8) * DM + cc) = l;
            } else if (MODE == 3) {
                if (br == bc) {
                    float* s0 = g_S + (size_t)r0 * SEQ + cc;
                    s0[0] = (cc + 0 <= r0) ? v00 * scale : -INFINITY;
                    s0[1] = (cc + 1 <= r0) ? v01 * scale : -INFINITY;
                    float* s1 = g_S + (size_t)(r0 + 8) * SEQ + cc;
                    s1[0] = (cc + 0 <= r0 + 8) ? v10 * scale : -INFINITY;
                    s1[1] = (cc + 1 <= r0 + 8) ? v11 * scale : -INFINITY;
                } else {
                    *(float2*)(g_S + (size_t)r0 * SEQ + cc)       = make_float2(v00 * scale, v01 * scale);
                    *(float2*)(g_S + (size_t)(r0 + 8) * SEQ + cc) = make_float2(v10 * scale, v11 * scale);
                }
            } else {
                *(float2*)(Oext + (size_t)r0 * DM + cc)       = make_float2(v00, v01);
                *(float2*)(Oext + (size_t)(r0 + 8) * DM + cc) = make_float2(v10, v11);
            }
        }
    }
}

// ---------------------------------------------------------------------------
// Row softmax over g_S; emits P hi/lo bf16. Row r covers [0, roundup128(r+1)).
// ---------------------------------------------------------------------------
__global__ __launch_bounds__(256) void softmax_kernel()
{
    const int r   = (int)blockIdx.x;
    const int L   = (((r >> 7) + 1) << 7);
    const float* row = g_S + (size_t)r * SEQ;
    const int tid = threadIdx.x;
    __shared__ float red[256];

    float v[16];
    int   cnt = 0;
    float mx  = -INFINITY;
    for (int c = tid; c < L; c += 256) {
        float t = row[c];
        v[cnt++] = t;
        mx = fmaxf(mx, t);
    }
    red[tid] = mx;
    __syncthreads();
#pragma unroll
    for (int s = 128; s > 0; s >>= 1) {
        if (tid < s) red[tid] = fmaxf(red[tid], red[tid + s]);
        __syncthreads();
    }
    mx = red[0];
    __syncthreads();

    float sum = 0.0f;
    for (int j = 0; j < cnt; j++) {
        v[j] = expf(v[j] - mx);
        sum += v[j];
    }
    red[tid] = sum;
    __syncthreads();
#pragma unroll
    for (int s = 128; s > 0; s >>= 1) {
        if (tid < s) red[tid] += red[tid + s];
        __syncthreads();
    }
    const float rinv = 1.0f / red[0];

    cnt = 0;
    for (int c = tid; c < L; c += 256) {
        float p = v[cnt++] * rinv;
        __nv_bfloat16 h, l; split1(p, h, l);
        g_Phi[(size_t)r * SEQ + c] = h;
        g_Plo[(size_t)r * SEQ + c] = l;
    }
}

// ---------------------------------------------------------------------------
extern "C" void kernel_launch(void* const* d_in, const int* in_sizes, int n_in,
                              void* d_out, int out_size)
{
    const float* x  = (const float*)d_in[0];
    const float* Wq = (const float*)d_in[1];
    const float* Wk = (const float*)d_in[2];
    const float* Wv = (const float*)d_in[3];
    float* out = (float*)d_out;
    (void)in_sizes; (void)n_in; (void)out_size;

    cudaFuncSetAttribute(hgemm<0>, cudaFuncAttributeMaxDynamicSharedMemorySize, SMEM_BYTES);
    cudaFuncSetAttribute(hgemm<3>, cudaFuncAttributeMaxDynamicSharedMemorySize, SMEM_BYTES);
    cudaFuncSetAttribute(hgemm<4>, cudaFuncAttributeMaxDynamicSharedMemorySize, SMEM_BYTES);

    // 0) operand prep
    xsplit_kernel<<<SEQ * DM / (256 * 4), 256>>>(x);
    wtrans_kernel<<<dim3(DM / 32, DM / 32, 3), dim3(32, 8)>>>(Wq, Wk, Wv);

    // 1) projections Q/K/V (z selects weight + destination)
    hgemm<0><<<dim3(DM / TN, SEQ / TM, 3), NTHREADS, SMEM_BYTES>>>(nullptr);

    // 2) causal scores (lower-triangular blocks only)
    const int nTri = (SEQ / TM) * (SEQ / TM + 1) / 2;   // 528
    hgemm<3><<<nTri, NTHREADS, SMEM_BYTES>>>(nullptr);

    // 3) softmax -> P hi/lo
    softmax_kernel<<<SEQ, 256>>>();

    // 4) O = P @ V
    hgemm<4><<<dim3(DM / TN, SEQ / TM), NTHREADS, SMEM_BYTES>>>(out);
}